// round 3
// baseline (speedup 1.0000x reference)
#include <cuda_runtime.h>
#include <cstddef>

// Problem shape (fixed by reference setup_inputs)
#define B_      16
#define T_      2048
#define D_      256
#define K_      8
#define TILE_T  32
#define CHUNKS  16                      // blocks per batch
#define TOK_PER_BLK (T_ / CHUNKS)       // 128 tokens per block
#define TILES_PER_BLK (TOK_PER_BLK / TILE_T)  // 4 tiles
#define LN_EPS  1e-5f

// Scratch accumulator: [b][k][0..255]=sum(w*x), [256..511]=sum(w*x^2), [512]=sum(w)
__device__ float g_acc[B_][K_][2 * D_ + 1];

// ---------------------------------------------------------------------------
// Kernel 1: zero the scratch accumulator
// ---------------------------------------------------------------------------
__global__ void ldep_zero_kernel() {
    int idx = blockIdx.x * blockDim.x + threadIdx.x;
    const int n = B_ * K_ * (2 * D_ + 1);
    float* p = &g_acc[0][0][0];
    if (idx < n) p[idx] = 0.0f;
}

// ---------------------------------------------------------------------------
// Kernel 2: fused soft-assignment + weighted accumulation
//   grid = (CHUNKS, B_), block = 256 threads (8 warps)
// ---------------------------------------------------------------------------
__global__ __launch_bounds__(256, 2)
void ldep_main_kernel(const float* __restrict__ x,
                      const float* __restrict__ centers,
                      const float* __restrict__ scale,
                      const float* __restrict__ temperature) {
    __shared__ float xs[TILE_T][D_];                 // 32 KB token tile
    __shared__ __align__(16) float ws[TILE_T][K_];   // per-token weights

    const int b     = blockIdx.y;
    const int chunk = blockIdx.x;
    const int tid   = threadIdx.x;
    const int lane  = tid & 31;
    const int warp  = tid >> 5;

    // Centers in registers for the dot loop: c_reg[k][i] = centers[k][lane + 32*i]
    // Also compute ||c_k||^2 once (warp reduce) and a_k = temperature * scale[k].
    const float tval = __ldg(temperature);
    float c_reg[K_][8];
    float c2[K_];
    float a_k[K_];
#pragma unroll
    for (int k = 0; k < K_; k++) {
        float p = 0.0f;
#pragma unroll
        for (int i = 0; i < 8; i++) {
            float c = __ldg(&centers[k * D_ + lane + 32 * i]);
            c_reg[k][i] = c;
            p += c * c;
        }
#pragma unroll
        for (int o = 16; o > 0; o >>= 1)
            p += __shfl_xor_sync(0xffffffffu, p, o);
        c2[k]  = p;
        a_k[k] = tval * __ldg(&scale[k]);
    }

    // Per-thread accumulators: thread owns dim d = tid for all 8 clusters.
    float acc_wx[K_], acc_wx2[K_];
#pragma unroll
    for (int k = 0; k < K_; k++) { acc_wx[k] = 0.0f; acc_wx2[k] = 0.0f; }
    float acc_w = 0.0f;  // meaningful for lane < K_ (cluster = lane), per warp

    const float* xb = x + ((size_t)b * T_ + (size_t)chunk * TOK_PER_BLK) * D_;

    for (int tile = 0; tile < TILES_PER_BLK; ++tile) {
        // ---- Stage 32x256 fp32 tile into smem (float4, coalesced) ----
        const float4* src = (const float4*)(xb + (size_t)tile * TILE_T * D_);
        float4* dst = (float4*)(&xs[0][0]);
#pragma unroll
        for (int i = 0; i < 8; i++)
            dst[tid + 256 * i] = src[tid + 256 * i];
        __syncthreads();

        // ---- Weight phase: warp w handles tokens w, w+8, w+16, w+24 ----
#pragma unroll
        for (int s = 0; s < 4; s++) {
            const int tok = warp + 8 * s;
            float dot[K_];
#pragma unroll
            for (int k = 0; k < K_; k++) dot[k] = 0.0f;
            float x2 = 0.0f;
#pragma unroll
            for (int i = 0; i < 8; i++) {
                float xv = xs[tok][lane + 32 * i];   // conflict-free (stride 32)
                x2 += xv * xv;
#pragma unroll
                for (int k = 0; k < K_; k++)
                    dot[k] += xv * c_reg[k][i];
            }
            // Butterfly reduce 9 values across the warp
#pragma unroll
            for (int o = 16; o > 0; o >>= 1) {
                x2 += __shfl_xor_sync(0xffffffffu, x2, o);
#pragma unroll
                for (int k = 0; k < K_; k++)
                    dot[k] += __shfl_xor_sync(0xffffffffu, dot[k], o);
            }
            // Softmax over K (redundant per lane — cheap, keeps lanes uniform)
            float lg[K_];
            float mx = -1e30f;
#pragma unroll
            for (int k = 0; k < K_; k++) {
                float dist = x2 - 2.0f * dot[k] + c2[k];
                lg[k] = -a_k[k] * dist;
                mx = fmaxf(mx, lg[k]);
            }
            float sum = 0.0f;
#pragma unroll
            for (int k = 0; k < K_; k++) {
                lg[k] = __expf(lg[k] - mx);
                sum += lg[k];
            }
            float inv = 1.0f / sum;
            if (lane < K_) {
                float wv = lg[lane] * inv;
                ws[tok][lane] = wv;
                acc_w += wv;                 // s_w partial for cluster = lane
            }
        }
        __syncthreads();

        // ---- Accumulate phase: thread tid owns dim d = tid ----
#pragma unroll 4
        for (int tok = 0; tok < TILE_T; ++tok) {
            float xv  = xs[tok][tid];
            float xv2 = xv * xv;
            const float4 w0 = *(const float4*)&ws[tok][0];  // smem broadcast
            const float4 w1 = *(const float4*)&ws[tok][4];
            acc_wx[0] += w0.x * xv;  acc_wx2[0] += w0.x * xv2;
            acc_wx[1] += w0.y * xv;  acc_wx2[1] += w0.y * xv2;
            acc_wx[2] += w0.z * xv;  acc_wx2[2] += w0.z * xv2;
            acc_wx[3] += w0.w * xv;  acc_wx2[3] += w0.w * xv2;
            acc_wx[4] += w1.x * xv;  acc_wx2[4] += w1.x * xv2;
            acc_wx[5] += w1.y * xv;  acc_wx2[5] += w1.y * xv2;
            acc_wx[6] += w1.z * xv;  acc_wx2[6] += w1.z * xv2;
            acc_wx[7] += w1.w * xv;  acc_wx2[7] += w1.w * xv2;
        }
        __syncthreads();  // before next tile overwrites xs/ws
    }

    // ---- Flush per-block partials to global accumulator ----
#pragma unroll
    for (int k = 0; k < K_; k++) {
        atomicAdd(&g_acc[b][k][tid],      acc_wx[k]);
        atomicAdd(&g_acc[b][k][D_ + tid], acc_wx2[k]);
    }
    if (lane < K_)
        atomicAdd(&g_acc[b][lane][2 * D_], acc_w);
}

// ---------------------------------------------------------------------------
// Kernel 3: finalize — mean/var from decomposed sums + LayerNorm(512) + write
//   grid = (K_, B_), block = 256 threads (one thread per dim)
// ---------------------------------------------------------------------------
__global__ __launch_bounds__(256)
void ldep_finalize_kernel(const float* __restrict__ centers,
                          float* __restrict__ out) {
    const int b   = blockIdx.y;
    const int k   = blockIdx.x;
    const int tid = threadIdx.x;
    const int lane = tid & 31, warp = tid >> 5;

    __shared__ float r1[8], r2[8];

    float sw   = g_acc[b][k][2 * D_];
    float swx  = g_acc[b][k][tid];
    float swx2 = g_acc[b][k][D_ + tid];
    float c    = __ldg(&centers[k * D_ + tid]);

    // Same algebraic decomposition as the reference (errors track exactly)
    float mean = swx - c * sw;
    float E    = swx2 - 2.0f * c * swx + c * c * sw;
    float var  = E - mean * mean;

    // LayerNorm stats over the 512 concatenated [mean | var] values
    float s1 = mean + var;
    float s2 = mean * mean + var * var;
#pragma unroll
    for (int o = 16; o > 0; o >>= 1) {
        s1 += __shfl_xor_sync(0xffffffffu, s1, o);
        s2 += __shfl_xor_sync(0xffffffffu, s2, o);
    }
    if (lane == 0) { r1[warp] = s1; r2[warp] = s2; }
    __syncthreads();
    float S1 = 0.0f, S2 = 0.0f;
#pragma unroll
    for (int i = 0; i < 8; i++) { S1 += r1[i]; S2 += r2[i]; }

    const float mu  = S1 * (1.0f / 512.0f);
    const float v   = S2 * (1.0f / 512.0f) - mu * mu;
    const float inv = rsqrtf(v + LN_EPS);

    float* o = out + ((size_t)b * K_ + k) * (2 * D_);
    o[tid]      = (mean - mu) * inv;
    o[D_ + tid] = (var  - mu) * inv;
}

// ---------------------------------------------------------------------------
// Launch: inputs per metadata order: x, centers, scale, temperature
// ---------------------------------------------------------------------------
extern "C" void kernel_launch(void* const* d_in, const int* in_sizes, int n_in,
                              void* d_out, int out_size) {
    const float* x           = (const float*)d_in[0];
    const float* centers     = (const float*)d_in[1];
    const float* scale       = (const float*)d_in[2];
    const float* temperature = (const float*)d_in[3];
    float* out               = (float*)d_out;

    const int nz = B_ * K_ * (2 * D_ + 1);
    ldep_zero_kernel<<<(nz + 255) / 256, 256>>>();
    ldep_main_kernel<<<dim3(CHUNKS, B_), 256>>>(x, centers, scale, temperature);
    ldep_finalize_kernel<<<dim3(K_, B_), 256>>>(centers, out);
}

// round 7
// speedup vs baseline: 1.0691x; 1.0691x over previous
#include <cuda_runtime.h>
#include <cstddef>
#include <cstdint>

// Problem shape (fixed by reference setup_inputs)
#define B_      16
#define T_      2048
#define D_      256
#define K_      8
#define CHUNKS  16                       // blocks per batch
#define TOK_PER_BLK (T_ / CHUNKS)        // 128 tokens per block
#define TILE_T  16
#define NTILES  (TOK_PER_BLK / TILE_T)   // 8 tiles
#define LN_EPS  1e-5f

using ull = unsigned long long;

// Per-(batch,chunk) partial sums: [k][0..255]=sum(w*x), [k][256..511]=sum(w*x^2)
__device__ float g_part[B_][CHUNKS][K_][2 * D_];
__device__ float g_sw[B_][CHUNKS][K_];   // sum of weights per cluster

// ---------------------------------------------------------------------------
// f32x2 packed helpers (sm_10x dual fp32 pipe — PTX only)
// ---------------------------------------------------------------------------
__device__ __forceinline__ ull pk2(float lo, float hi) {
    ull r; asm("mov.b64 %0, {%1, %2};" : "=l"(r) : "f"(lo), "f"(hi)); return r;
}
__device__ __forceinline__ float2 unpk(ull v) {
    float2 r; asm("mov.b64 {%0, %1}, %2;" : "=f"(r.x), "=f"(r.y) : "l"(v)); return r;
}
__device__ __forceinline__ ull fma2(ull a, ull b, ull c) {
    ull d; asm("fma.rn.f32x2 %0, %1, %2, %3;" : "=l"(d) : "l"(a), "l"(b), "l"(c)); return d;
}
__device__ __forceinline__ ull mul2(ull a, ull b) {
    ull d; asm("mul.rn.f32x2 %0, %1, %2;" : "=l"(d) : "l"(a), "l"(b)); return d;
}

// ---------------------------------------------------------------------------
// cp.async helpers
// ---------------------------------------------------------------------------
__device__ __forceinline__ void cp_async16(unsigned int saddr, const void* gptr) {
    asm volatile("cp.async.cg.shared.global [%0], [%1], 16;" :: "r"(saddr), "l"(gptr));
}
#define CP_COMMIT() asm volatile("cp.async.commit_group;" ::: "memory")
#define CP_WAIT0()  asm volatile("cp.async.wait_group 0;"  ::: "memory")

// ---------------------------------------------------------------------------
// Main fused kernel: grid (CHUNKS, B_), 256 threads
// ---------------------------------------------------------------------------
__global__ __launch_bounds__(256, 2)
void ldep_main_kernel(const float* __restrict__ x,
                      const float* __restrict__ centers,
                      const float* __restrict__ scale,
                      const float* __restrict__ temperature) {
    __shared__ float  xs[2][TILE_T][D_];                // 2 x 16 KB tile buffers
    __shared__ __align__(16) float2 ws2[TILE_T][K_];    // weights duplicated (w,w)
    __shared__ float swred[8][K_];

    const int b     = blockIdx.y;
    const int chunk = blockIdx.x;
    const int tid   = threadIdx.x;
    const int lane  = tid & 31;
    const int warp  = tid >> 5;

    // ---- Init: centers in packed registers; per-lane selected c2/a ----
    const float tval = __ldg(temperature);
    ull c2r[K_][4];
    float c2n[K_];   // ||c_k||^2 (full, all lanes)
#pragma unroll
    for (int k = 0; k < K_; k++) {
        const float4* cr = (const float4*)&centers[k * D_];
        float4 ca = __ldg(&cr[lane]);
        float4 cb = __ldg(&cr[lane + 32]);
        c2r[k][0] = pk2(ca.x, ca.y);
        c2r[k][1] = pk2(ca.z, ca.w);
        c2r[k][2] = pk2(cb.x, cb.y);
        c2r[k][3] = pk2(cb.z, cb.w);
        ull n = fma2(c2r[k][0], c2r[k][0],
                fma2(c2r[k][1], c2r[k][1],
                fma2(c2r[k][2], c2r[k][2],
                mul2(c2r[k][3], c2r[k][3]))));
        float2 nn = unpk(n);
        float p = nn.x + nn.y;
#pragma unroll
        for (int o = 16; o > 0; o >>= 1)
            p += __shfl_xor_sync(0xffffffffu, p, o);
        c2n[k] = p;
    }
    const int kk = lane & 7;
    float c2sel = c2n[0];
#pragma unroll
    for (int j = 1; j < K_; j++) c2sel = (kk == j) ? c2n[j] : c2sel;
    float asel = tval * __ldg(&scale[0]);
#pragma unroll
    for (int j = 1; j < K_; j++) {
        float a = tval * __ldg(&scale[j]);
        asel = (kk == j) ? a : asel;
    }

    // ---- Persistent accumulators ----
    // Accumulate phase: thread owns dim pair p = tid&127 -> dims (2p,2p+1),
    // and cluster half h = tid>>7 -> clusters 4h..4h+3.
    const int p = tid & 127;
    const int h = tid >> 7;
    ull acc_wx[4], acc_wx2[4];
#pragma unroll
    for (int j = 0; j < 4; j++) { acc_wx[j] = 0ull; acc_wx2[j] = 0ull; }
    float acc_w = 0.0f;   // lane<8: partial s_w for cluster=lane (per warp)

    const float* xb = x + ((size_t)b * T_ + (size_t)chunk * TOK_PER_BLK) * D_;

    // Prefetch tile 0
    {
        const float4* src = (const float4*)xb;
        unsigned int dst = (unsigned int)__cvta_generic_to_shared(&xs[0][0][0]);
#pragma unroll
        for (int i = 0; i < 4; i++)
            cp_async16(dst + (unsigned int)(tid + 256 * i) * 16u, src + tid + 256 * i);
        CP_COMMIT();
    }

    for (int t = 0; t < NTILES; ++t) {
        const int bsel = t & 1;
        CP_WAIT0();
        __syncthreads();

        // Prefetch next tile (overlaps with weight+accum below)
        if (t + 1 < NTILES) {
            const float4* src = (const float4*)(xb + (size_t)(t + 1) * TILE_T * D_);
            unsigned int dst = (unsigned int)__cvta_generic_to_shared(&xs[(t + 1) & 1][0][0]);
#pragma unroll
            for (int i = 0; i < 4; i++)
                cp_async16(dst + (unsigned int)(tid + 256 * i) * 16u, src + tid + 256 * i);
            CP_COMMIT();
        }

        // ---- Weight phase: warp w handles tokens w, w+8 ----
#pragma unroll
        for (int s = 0; s < 2; ++s) {
            const int tok = warp + 8 * s;
            const float4* xr = (const float4*)&xs[bsel][tok][0];
            float4 a  = xr[lane];
            float4 b4 = xr[lane + 32];
            ull xA0 = pk2(a.x, a.y),   xA1 = pk2(a.z, a.w);
            ull xB0 = pk2(b4.x, b4.y), xB1 = pk2(b4.z, b4.w);

            float red[9];
            {
                ull x2p = fma2(xA0, xA0, fma2(xA1, xA1,
                          fma2(xB0, xB0, mul2(xB1, xB1))));
                float2 u = unpk(x2p);
                red[8] = u.x + u.y;
            }
#pragma unroll
            for (int k = 0; k < K_; k++) {
                ull d = fma2(c2r[k][0], xA0, fma2(c2r[k][1], xA1,
                        fma2(c2r[k][2], xB0, mul2(c2r[k][3], xB1))));
                float2 u = unpk(d);
                red[k] = u.x + u.y;
            }
            // Butterfly reduce 9 values; afterwards every lane has all sums
#pragma unroll
            for (int o = 16; o > 0; o >>= 1)
#pragma unroll
                for (int j = 0; j < 9; j++)
                    red[j] += __shfl_xor_sync(0xffffffffu, red[j], o);

            // Lane k computes its own logit (one exp per token instead of 8)
            float dsel = red[0];
#pragma unroll
            for (int j = 1; j < K_; j++) dsel = (kk == j) ? red[j] : dsel;
            float dist = red[8] - 2.0f * dsel + c2sel;
            float lg = -asel * dist;
            float mx = lg;
            mx = fmaxf(mx, __shfl_xor_sync(0xffffffffu, mx, 1));
            mx = fmaxf(mx, __shfl_xor_sync(0xffffffffu, mx, 2));
            mx = fmaxf(mx, __shfl_xor_sync(0xffffffffu, mx, 4));
            float e = __expf(lg - mx);
            float sm = e;
            sm += __shfl_xor_sync(0xffffffffu, sm, 1);
            sm += __shfl_xor_sync(0xffffffffu, sm, 2);
            sm += __shfl_xor_sync(0xffffffffu, sm, 4);
            float wv = __fdividef(e, sm);
            if (lane < K_) {
                ws2[tok][lane] = make_float2(wv, wv);
                acc_w += wv;
            }
        }
        __syncthreads();

        // ---- Accumulate phase (packed f32x2) ----
#pragma unroll 4
        for (int tok = 0; tok < TILE_T; ++tok) {
            ull xv = *(const ull*)&xs[bsel][tok][2 * p];   // dims (2p, 2p+1)
            ull xq = mul2(xv, xv);
            const ulonglong2* wr = (const ulonglong2*)&ws2[tok][4 * h];
            ulonglong2 wA = wr[0];   // (w[4h],w[4h]) (w[4h+1],w[4h+1])
            ulonglong2 wB = wr[1];
            acc_wx[0]  = fma2(wA.x, xv, acc_wx[0]);
            acc_wx2[0] = fma2(wA.x, xq, acc_wx2[0]);
            acc_wx[1]  = fma2(wA.y, xv, acc_wx[1]);
            acc_wx2[1] = fma2(wA.y, xq, acc_wx2[1]);
            acc_wx[2]  = fma2(wB.x, xv, acc_wx[2]);
            acc_wx2[2] = fma2(wB.x, xq, acc_wx2[2]);
            acc_wx[3]  = fma2(wB.y, xv, acc_wx[3]);
            acc_wx2[3] = fma2(wB.y, xq, acc_wx2[3]);
        }
    }

    // ---- Flush per-block partials (disjoint slots, no atomics) ----
#pragma unroll
    for (int j = 0; j < 4; j++) {
        const int k = 4 * h + j;
        float* base = &g_part[b][chunk][k][0];
        float2 vx = unpk(acc_wx[j]);
        float2 vq = unpk(acc_wx2[j]);
        *(float2*)(base + 2 * p)      = vx;
        *(float2*)(base + D_ + 2 * p) = vq;
    }
    if (lane < K_) swred[warp][lane] = acc_w;
    __syncthreads();
    if (tid < K_) {
        float s = 0.0f;
#pragma unroll
        for (int w = 0; w < 8; w++) s += swred[w][tid];
        g_sw[b][chunk][tid] = s;
    }
}

// ---------------------------------------------------------------------------
// Finalize: reduce 16 chunk-partials, mean/var decomposition, LayerNorm(512)
//   grid = (K_, B_), 256 threads (one dim each)
// ---------------------------------------------------------------------------
__global__ __launch_bounds__(256)
void ldep_finalize_kernel(const float* __restrict__ centers,
                          float* __restrict__ out) {
    const int b    = blockIdx.y;
    const int k    = blockIdx.x;
    const int tid  = threadIdx.x;
    const int lane = tid & 31, warp = tid >> 5;

    __shared__ float r1[8], r2[8];

    float sw = 0.0f, swx = 0.0f, swx2 = 0.0f;
#pragma unroll
    for (int c = 0; c < CHUNKS; c++) {
        sw   += g_sw[b][c][k];                 // uniform -> broadcast load
        swx  += g_part[b][c][k][tid];
        swx2 += g_part[b][c][k][D_ + tid];
    }
    float cc = __ldg(&centers[k * D_ + tid]);

    // Same algebraic decomposition as the reference
    float mean = swx - cc * sw;
    float E    = swx2 - 2.0f * cc * swx + cc * cc * sw;
    float var  = E - mean * mean;

    // LayerNorm stats over the 512 concatenated [mean | var] values
    float s1 = mean + var;
    float s2 = mean * mean + var * var;
#pragma unroll
    for (int o = 16; o > 0; o >>= 1) {
        s1 += __shfl_xor_sync(0xffffffffu, s1, o);
        s2 += __shfl_xor_sync(0xffffffffu, s2, o);
    }
    if (lane == 0) { r1[warp] = s1; r2[warp] = s2; }
    __syncthreads();
    float S1 = 0.0f, S2 = 0.0f;
#pragma unroll
    for (int i = 0; i < 8; i++) { S1 += r1[i]; S2 += r2[i]; }

    const float mu  = S1 * (1.0f / 512.0f);
    const float v   = S2 * (1.0f / 512.0f) - mu * mu;
    const float inv = rsqrtf(v + LN_EPS);

    float* o = out + ((size_t)b * K_ + k) * (2 * D_);
    o[tid]      = (mean - mu) * inv;
    o[D_ + tid] = (var  - mu) * inv;
}

// ---------------------------------------------------------------------------
// Launch: inputs per metadata order: x, centers, scale, temperature
// ---------------------------------------------------------------------------
extern "C" void kernel_launch(void* const* d_in, const int* in_sizes, int n_in,
                              void* d_out, int out_size) {
    const float* x           = (const float*)d_in[0];
    const float* centers     = (const float*)d_in[1];
    const float* scale       = (const float*)d_in[2];
    const float* temperature = (const float*)d_in[3];
    float* out               = (float*)d_out;

    ldep_main_kernel<<<dim3(CHUNKS, B_), 256>>>(x, centers, scale, temperature);
    ldep_finalize_kernel<<<dim3(K_, B_), 256>>>(centers, out);
}